// round 9
// baseline (speedup 1.0000x reference)
#include <cuda_runtime.h>
#include <math_constants.h>
#include <cstdint>

#define SQ 2048
#define NB 4
#define ND 256
#define NE 256
#define NH 8
#define HD 32
#define MROWS (SQ*NB)       // 8192
#define LDQKV (3*NE)        // 768

// ---------------- scratch (device globals; no allocation) ----------------
__device__ __align__(16) float g_Weff[3*NE*ND];
__device__ __align__(16) float g_beff[3*NE];
__device__ __align__(16) float g_Wcomb[ND*NE];
__device__ __align__(16) float g_bcomb[ND];
__device__ __align__(16) float g_qkv[(size_t)MROWS*LDQKV];
__device__ __align__(16) float g_ctx[(size_t)MROWS*NE];
__device__ __align__(16) float g_y[(size_t)MROWS*ND];

extern __shared__ float sdyn[];

// ---------------- helpers ----------------
__device__ __forceinline__ void mma_tf32(float c[4],
                                         uint32_t a0, uint32_t a1, uint32_t a2, uint32_t a3,
                                         uint32_t b0, uint32_t b1)
{
    asm volatile("mma.sync.aligned.m16n8k8.row.col.f32.tf32.tf32.f32 "
                 "{%0,%1,%2,%3}, {%4,%5,%6,%7}, {%8,%9}, {%0,%1,%2,%3};"
                 : "+f"(c[0]), "+f"(c[1]), "+f"(c[2]), "+f"(c[3])
                 : "r"(a0), "r"(a1), "r"(a2), "r"(a3), "r"(b0), "r"(b1));
}

__device__ __forceinline__ void cp16(void* smem_dst, const void* gmem_src) {
    uint32_t sa = (uint32_t)__cvta_generic_to_shared(smem_dst);
    asm volatile("cp.async.cg.shared.global [%0], [%1], 16;\n" :: "r"(sa), "l"(gmem_src));
}

// ---------------- prep: 4 small 256^3 products + bias folds ----------------
// z<4 : weight products (SIMT 64x64 tiles).  z==4 : bias folds (16 blocks x 64 outputs).
__global__ void prep_gemmAB(const float* __restrict__ Win,
                            const float* __restrict__ Wq, const float* __restrict__ Wk,
                            const float* __restrict__ Wv, const float* __restrict__ Wfc,
                            const float* __restrict__ Wout,
                            const float* __restrict__ bin_, const float* __restrict__ bq,
                            const float* __restrict__ bk, const float* __restrict__ bv,
                            const float* __restrict__ bout, const float* __restrict__ bfc)
{
    const int t = threadIdx.x;
    if (blockIdx.z == 4) {
        // ---- bias folds: 1024 outputs over 16 blocks ----
        int xb = blockIdx.y * 4 + blockIdx.x;      // 0..15
        int warp = t >> 5, lane = t & 31;
        #pragma unroll
        for (int o = 0; o < 8; o++) {
            int wid = xb * 64 + warp * 8 + o;      // 0..1023
            const float* row; const float* vec; float base;
            if (wid < 3*NE) {
                int tt = wid >> 8;
                row = Win + (size_t)wid * NE;
                vec = (tt == 0) ? bq : (tt == 1) ? bk : bv;
                base = bin_[wid];
            } else {
                int r = wid - 3*NE;
                row = Wfc + (size_t)r * NE;
                vec = bout;
                base = bfc[r];
            }
            float s = 0.f;
            #pragma unroll
            for (int u = 0; u < 8; u++) s += row[u*32 + lane] * vec[u*32 + lane];
            #pragma unroll
            for (int off = 16; off >= 1; off >>= 1) s += __shfl_xor_sync(0xffffffffu, s, off);
            if (lane == 0) {
                if (wid < 3*NE) g_beff[wid] = base + s;
                else            g_bcomb[wid - 3*NE] = base + s;
            }
        }
        return;
    }

    __shared__ __align__(16) float As[16][68];   // [c][r]
    __shared__ __align__(16) float Bs[16][68];   // [c][d]
    const int tt = blockIdx.z;
    const float* A; const float* B; float* C;
    if (tt < 3) { A = Win + (size_t)tt*NE*NE; B = (tt==0)?Wq:(tt==1)?Wk:Wv; C = g_Weff + (size_t)tt*NE*ND; }
    else        { A = Wfc; B = Wout; C = g_Wcomb; }

    const int m0  = blockIdx.y * 64;
    const int d0  = blockIdx.x * 64;
    const int lrow = t >> 2;
    const int lc4  = (t & 3) << 2;
    const int brow = t >> 4;
    const int bc4  = (t & 15) << 2;
    const int ty = t >> 4, tx = t & 15;

    float acc[4][4] = {};
    for (int k0 = 0; k0 < NE; k0 += 16) {
        float4 av = *(const float4*)&A[(size_t)(m0 + lrow)*NE + k0 + lc4];
        As[lc4+0][lrow] = av.x; As[lc4+1][lrow] = av.y;
        As[lc4+2][lrow] = av.z; As[lc4+3][lrow] = av.w;
        *(float4*)&Bs[brow][bc4] = *(const float4*)&B[(size_t)(k0 + brow)*NE + d0 + bc4];
        __syncthreads();
        #pragma unroll
        for (int kk = 0; kk < 16; kk++) {
            float4 a4 = *(const float4*)&As[kk][ty << 2];
            float4 b4 = *(const float4*)&Bs[kk][tx << 2];
            float ar[4] = {a4.x, a4.y, a4.z, a4.w};
            float br[4] = {b4.x, b4.y, b4.z, b4.w};
            #pragma unroll
            for (int i = 0; i < 4; i++)
                #pragma unroll
                for (int j = 0; j < 4; j++)
                    acc[i][j] += ar[i] * br[j];
        }
        __syncthreads();
    }
    #pragma unroll
    for (int i = 0; i < 4; i++) {
        float4 o = {acc[i][0], acc[i][1], acc[i][2], acc[i][3]};
        *(float4*)&C[(size_t)(m0 + (ty<<2) + i)*NE + d0 + (tx<<2)] = o;
    }
}

// ---------------- tensor-core GEMM, 3-stage cp.async pipeline ----------------
// C[M,N] = A[M,K] @ W[N,K]^T + bias (+resid). Block tile 128x128, BK=32,
// 256 threads, warp tile 64x32. One __syncthreads per K-tile.
#define GST 36
#define GSTAGE (128*GST)
#define GEMM_SMEM (6*GSTAGE*(int)sizeof(float))   // 3 stages * (A+B) = 110592 B
__global__ void __launch_bounds__(256) gemm_mma(const float* __restrict__ A,
                                                const float* __restrict__ W,
                                                const float* __restrict__ bias,
                                                const float* __restrict__ resid,
                                                float* __restrict__ C, int N, int K)
{
    const int tid = threadIdx.x;
    const int m0 = blockIdx.y * 128;
    const int n0 = blockIdx.x * 128;
    const int warp = tid >> 5;
    const int lane = tid & 31;
    const int wm = warp >> 2;
    const int wn = warp & 3;
    const int grp = lane >> 2;
    const int tig = lane & 3;
    const int ldr = tid >> 3;
    const int ldc = (tid & 7) << 2;

    const int T = K >> 5;
    float acc[4][4][4] = {};

    // prefetch stages 0,1
    #pragma unroll
    for (int s = 0; s < 2; s++) {
        float* As = sdyn + s*2*GSTAGE;
        float* Bs = As + GSTAGE;
        int k0 = s << 5;
        #pragma unroll
        for (int p = 0; p < 4; p++) {
            int row = ldr + p * 32;
            cp16(&As[row*GST + ldc], &A[(size_t)(m0 + row)*K + k0 + ldc]);
            cp16(&Bs[row*GST + ldc], &W[(size_t)(n0 + row)*K + k0 + ldc]);
        }
        asm volatile("cp.async.commit_group;\n");
    }

    for (int t = 0; t < T; t++) {
        if (t + 1 < T) asm volatile("cp.async.wait_group 1;\n");
        else           asm volatile("cp.async.wait_group 0;\n");
        __syncthreads();

        if (t + 2 < T) {
            int s = (t + 2) % 3;
            int k0 = (t + 2) << 5;
            float* As = sdyn + s*2*GSTAGE;
            float* Bs = As + GSTAGE;
            #pragma unroll
            for (int p = 0; p < 4; p++) {
                int row = ldr + p * 32;
                cp16(&As[row*GST + ldc], &A[(size_t)(m0 + row)*K + k0 + ldc]);
                cp16(&Bs[row*GST + ldc], &W[(size_t)(n0 + row)*K + k0 + ldc]);
            }
            asm volatile("cp.async.commit_group;\n");
        }

        const float* As = sdyn + (t % 3)*2*GSTAGE;
        const float* Bs = As + GSTAGE;
        #pragma unroll
        for (int kk = 0; kk < 32; kk += 8) {
            uint32_t af[4][4], bf[4][2];
            #pragma unroll
            for (int mt = 0; mt < 4; mt++) {
                int r = (wm*64 + mt*16 + grp) * GST;
                af[mt][0] = __float_as_uint(As[r + kk + tig]);
                af[mt][1] = __float_as_uint(As[r + 8*GST + kk + tig]);
                af[mt][2] = __float_as_uint(As[r + kk + 4 + tig]);
                af[mt][3] = __float_as_uint(As[r + 8*GST + kk + 4 + tig]);
            }
            #pragma unroll
            for (int nt = 0; nt < 4; nt++) {
                int c = (wn*32 + nt*8 + grp) * GST;
                bf[nt][0] = __float_as_uint(Bs[c + kk + tig]);
                bf[nt][1] = __float_as_uint(Bs[c + kk + 4 + tig]);
            }
            #pragma unroll
            for (int mt = 0; mt < 4; mt++)
                #pragma unroll
                for (int nt = 0; nt < 4; nt++)
                    mma_tf32(acc[mt][nt], af[mt][0], af[mt][1], af[mt][2], af[mt][3],
                             bf[nt][0], bf[nt][1]);
        }
    }

    #pragma unroll
    for (int mt = 0; mt < 4; mt++) {
        #pragma unroll
        for (int nt = 0; nt < 4; nt++) {
            int col = n0 + wn*32 + nt*8 + 2*tig;
            float bx = bias[col], by = bias[col + 1];
            int r0 = m0 + wm*64 + mt*16 + grp;
            float2 o0 = {acc[mt][nt][0] + bx, acc[mt][nt][1] + by};
            float2 o1 = {acc[mt][nt][2] + bx, acc[mt][nt][3] + by};
            if (resid) {
                float2 r0v = *(const float2*)&resid[(size_t)r0 * N + col];
                float2 r1v = *(const float2*)&resid[(size_t)(r0 + 8) * N + col];
                o0.x += r0v.x; o0.y += r0v.y;
                o1.x += r1v.x; o1.y += r1v.y;
            }
            *(float2*)&C[(size_t)r0 * N + col] = o0;
            *(float2*)&C[(size_t)(r0 + 8) * N + col] = o1;
        }
    }
}

// ---------------- banded attention via tensor cores ----------------
// Block: 128 queries x one (b,h), 256 threads (8 warps), warp owns 16 queries.
// Per warp: S[16x64] = Q @ K^T over a 64-key window starting at wbase+w*16,
// masked softmax in registers, C[16x32] = P @ V. Supports req <= 24.
#define KST 36     // sK row stride
#define VST 180    // sVT row stride (mod 32 = 20, conflict-free frag reads)
#define QST 36     // sQ row stride
#define PST 68     // sP row stride
#define KROWS 176
#define SK_F   (KROWS*KST)           // 6336
#define SVT_F  (32*VST)              // 5760
#define SU_F   (8*16*PST)            // 8704 (>= 128*QST = 4608)
#define ATTN_SMEM ((SK_F + SVT_F + SU_F)*(int)sizeof(float))   // 83200 B
__global__ void __launch_bounds__(256) attn_mma(const int* __restrict__ reqp,
                                                float* __restrict__ ctx)
{
    float* sK  = sdyn;
    float* sVT = sdyn + SK_F;
    float* sU  = sdyn + SK_F + SVT_F;

    const float* qkv = g_qkv;
    const int req = *reqp;
    const int bh = blockIdx.y;
    const int b = bh >> 3;
    const int hoff = (bh & 7) * HD;
    const int q0 = blockIdx.x * 128;
    const int wbase = q0 - (req - 1);

    const int tid = threadIdx.x;
    const int w = tid >> 5;
    const int lane = tid & 31;
    const int grp = lane >> 2;
    const int tig = lane & 3;
    const float scale = rsqrtf((float)HD);

    // ---- stage Q (scaled), K, V^T (raw f32; MMA truncates to tf32) ----
    #pragma unroll
    for (int u = tid; u < 128*8; u += 256) {         // Q: 128 rows x 8 float4
        int r = u >> 3, c4 = (u & 7) << 2;
        float4 v = *(const float4*)&qkv[(size_t)((q0 + r)*NB + b)*LDQKV + hoff + c4];
        sU[r*QST + c4 + 0] = v.x * scale;
        sU[r*QST + c4 + 1] = v.y * scale;
        sU[r*QST + c4 + 2] = v.z * scale;
        sU[r*QST + c4 + 3] = v.w * scale;
    }
    for (int u = tid; u < KROWS*8; u += 256) {       // K + V: 176 rows x 8 float4
        int r = u >> 3, c4 = (u & 7) << 2;
        int key = wbase + r;
        float4 kv = {0.f, 0.f, 0.f, 0.f}, vv = {0.f, 0.f, 0.f, 0.f};
        if (key >= 0 && key < SQ) {
            size_t base = (size_t)(key*NB + b)*LDQKV + hoff + c4;
            kv = *(const float4*)&qkv[base + NE];
            vv = *(const float4*)&qkv[base + 2*NE];
        }
        sK[r*KST + c4 + 0] = kv.x;
        sK[r*KST + c4 + 1] = kv.y;
        sK[r*KST + c4 + 2] = kv.z;
        sK[r*KST + c4 + 3] = kv.w;
        sVT[(c4+0)*VST + r] = vv.x;
        sVT[(c4+1)*VST + r] = vv.y;
        sVT[(c4+2)*VST + r] = vv.z;
        sVT[(c4+3)*VST + r] = vv.w;
    }
    __syncthreads();

    // ---- scores: S[16x64] = Q @ K^T (keys wbase + w*16 + 0..63) ----
    float sc[8][4] = {};
    #pragma unroll
    for (int ks = 0; ks < 4; ks++) {
        int kk = ks * 8;
        uint32_t af[4], bf[8][2];
        {
            int r = (w*16 + grp) * QST;
            af[0] = __float_as_uint(sU[r + kk + tig]);
            af[1] = __float_as_uint(sU[r + 8*QST + kk + tig]);
            af[2] = __float_as_uint(sU[r + kk + 4 + tig]);
            af[3] = __float_as_uint(sU[r + 8*QST + kk + 4 + tig]);
        }
        #pragma unroll
        for (int nt = 0; nt < 8; nt++) {
            int r = (w*16 + nt*8 + grp) * KST;
            bf[nt][0] = __float_as_uint(sK[r + kk + tig]);
            bf[nt][1] = __float_as_uint(sK[r + kk + 4 + tig]);
        }
        #pragma unroll
        for (int nt = 0; nt < 8; nt++)
            mma_tf32(sc[nt], af[0], af[1], af[2], af[3], bf[nt][0], bf[nt][1]);
    }

    // ---- mask + softmax (registers) ----
    const int iw = q0 + w*16;
    const int jw = wbase + w*16;
    float mx0 = -CUDART_INF_F, mx1 = -CUDART_INF_F;
    {
        int i0 = iw + grp, i1 = i0 + 8;
        #pragma unroll
        for (int nt = 0; nt < 8; nt++) {
            int j0 = jw + nt*8 + 2*tig;
            int j1 = j0 + 1;
            bool g0 = (j0 >= 0) & (j0 < SQ);
            bool g1 = (j1 >= 0) & (j1 < SQ);
            float* c = sc[nt];
            c[0] = (g0 && abs(i0 - j0) < req) ? c[0] : -CUDART_INF_F;
            c[1] = (g1 && abs(i0 - j1) < req) ? c[1] : -CUDART_INF_F;
            c[2] = (g0 && abs(i1 - j0) < req) ? c[2] : -CUDART_INF_F;
            c[3] = (g1 && abs(i1 - j1) < req) ? c[3] : -CUDART_INF_F;
            mx0 = fmaxf(mx0, fmaxf(c[0], c[1]));
            mx1 = fmaxf(mx1, fmaxf(c[2], c[3]));
        }
    }
    #pragma unroll
    for (int o = 1; o <= 2; o <<= 1) {
        mx0 = fmaxf(mx0, __shfl_xor_sync(0xffffffffu, mx0, o));
        mx1 = fmaxf(mx1, __shfl_xor_sync(0xffffffffu, mx1, o));
    }
    float s0 = 0.f, s1 = 0.f;
    #pragma unroll
    for (int nt = 0; nt < 8; nt++) {
        float* c = sc[nt];
        c[0] = __expf(c[0] - mx0);
        c[1] = __expf(c[1] - mx0);
        c[2] = __expf(c[2] - mx1);
        c[3] = __expf(c[3] - mx1);
        s0 += c[0] + c[1];
        s1 += c[2] + c[3];
    }
    #pragma unroll
    for (int o = 1; o <= 2; o <<= 1) {
        s0 += __shfl_xor_sync(0xffffffffu, s0, o);
        s1 += __shfl_xor_sync(0xffffffffu, s1, o);
    }
    float rs0 = 1.f / s0, rs1 = 1.f / s1;

    // ---- store P into union region (overwrites Q) ----
    __syncthreads();   // all warps done reading sQ
    float* sP = sU + w * (16*PST);
    #pragma unroll
    for (int nt = 0; nt < 8; nt++) {
        float* c = sc[nt];
        int r0 = grp * PST + nt*8 + 2*tig;
        *(float2*)&sP[r0]           = make_float2(c[0], c[1]);
        *(float2*)&sP[r0 + 8*PST]   = make_float2(c[2], c[3]);
    }
    __syncwarp();

    // ---- ctx: C[16x32] = P[16x64] @ V[64x32] ----
    float ao[4][4] = {};
    #pragma unroll
    for (int ks = 0; ks < 8; ks++) {
        int kk = ks * 8;
        uint32_t af[4], bf[4][2];
        af[0] = __float_as_uint(sP[grp*PST + kk + tig]);
        af[1] = __float_as_uint(sP[(grp+8)*PST + kk + tig]);
        af[2] = __float_as_uint(sP[grp*PST + kk + 4 + tig]);
        af[3] = __float_as_uint(sP[(grp+8)*PST + kk + 4 + tig]);
        #pragma unroll
        for (int nt = 0; nt < 4; nt++) {
            int r = (nt*8 + grp) * VST + w*16;
            bf[nt][0] = __float_as_uint(sVT[r + kk + tig]);
            bf[nt][1] = __float_as_uint(sVT[r + kk + 4 + tig]);
        }
        #pragma unroll
        for (int nt = 0; nt < 4; nt++)
            mma_tf32(ao[nt], af[0], af[1], af[2], af[3], bf[nt][0], bf[nt][1]);
    }

    // ---- epilogue: divide by row sums, write ctx ----
    {
        int i0 = iw + grp;
        #pragma unroll
        for (int nt = 0; nt < 4; nt++) {
            int dcol = hoff + nt*8 + 2*tig;
            float2 o0 = {ao[nt][0] * rs0, ao[nt][1] * rs0};
            float2 o1 = {ao[nt][2] * rs1, ao[nt][3] * rs1};
            *(float2*)&ctx[(size_t)(i0*NB + b)*NE + dcol] = o0;
            *(float2*)&ctx[(size_t)((i0 + 8)*NB + b)*NE + dcol] = o1;
        }
    }
}

// ---------------- layernorm (warp per row of 256, float4) ----------------
__global__ void ln_kernel(const float* __restrict__ gamma, const float* __restrict__ beta,
                          float* __restrict__ out)
{
    int row = blockIdx.x * 8 + (threadIdx.x >> 5);
    int lane = threadIdx.x & 31;
    const float* yr = g_y + (size_t)row * ND;
    float4 a = *(const float4*)&yr[lane * 4];
    float4 c = *(const float4*)&yr[128 + lane * 4];
    float s  = a.x + a.y + a.z + a.w + c.x + c.y + c.z + c.w;
    float s2 = a.x*a.x + a.y*a.y + a.z*a.z + a.w*a.w
             + c.x*c.x + c.y*c.y + c.z*c.z + c.w*c.w;
    #pragma unroll
    for (int o = 16; o >= 1; o >>= 1) {
        s  += __shfl_xor_sync(0xffffffffu, s, o);
        s2 += __shfl_xor_sync(0xffffffffu, s2, o);
    }
    float mu  = s * (1.f / ND);
    float var = s2 * (1.f / ND) - mu * mu;
    float inv = rsqrtf(var + 1e-6f);
    float4 g0 = *(const float4*)&gamma[lane * 4];
    float4 g1 = *(const float4*)&gamma[128 + lane * 4];
    float4 b0 = *(const float4*)&beta[lane * 4];
    float4 b1 = *(const float4*)&beta[128 + lane * 4];
    float4 o0 = {(a.x - mu)*inv*g0.x + b0.x, (a.y - mu)*inv*g0.y + b0.y,
                 (a.z - mu)*inv*g0.z + b0.z, (a.w - mu)*inv*g0.w + b0.w};
    float4 o1 = {(c.x - mu)*inv*g1.x + b1.x, (c.y - mu)*inv*g1.y + b1.y,
                 (c.z - mu)*inv*g1.z + b1.z, (c.w - mu)*inv*g1.w + b1.w};
    *(float4*)&out[(size_t)row * ND + lane * 4] = o0;
    *(float4*)&out[(size_t)row * ND + 128 + lane * 4] = o1;
}

// ---------------- launch ----------------
extern "C" void kernel_launch(void* const* d_in, const int* in_sizes, int n_in,
                              void* d_out, int out_size)
{
    const float* mod  = (const float*)d_in[0];
    const float* Wq   = (const float*)d_in[2];
    const float* bq   = (const float*)d_in[3];
    const float* Wk   = (const float*)d_in[4];
    const float* bk   = (const float*)d_in[5];
    const float* Wv   = (const float*)d_in[6];
    const float* bv   = (const float*)d_in[7];
    const float* Win  = (const float*)d_in[8];
    const float* bin_ = (const float*)d_in[9];
    const float* Wout = (const float*)d_in[10];
    const float* bout = (const float*)d_in[11];
    const float* Wfc  = (const float*)d_in[12];
    const float* bfc  = (const float*)d_in[13];
    const float* gamma= (const float*)d_in[14];
    const float* beta = (const float*)d_in[15];
    const int*   req  = (const int*)d_in[16];
    float* out = (float*)d_out;

    float *dWeff, *dbeff, *dWcomb, *dbcomb, *dqkv, *dctx, *dy;
    cudaGetSymbolAddress((void**)&dWeff,  g_Weff);
    cudaGetSymbolAddress((void**)&dbeff,  g_beff);
    cudaGetSymbolAddress((void**)&dWcomb, g_Wcomb);
    cudaGetSymbolAddress((void**)&dbcomb, g_bcomb);
    cudaGetSymbolAddress((void**)&dqkv,   g_qkv);
    cudaGetSymbolAddress((void**)&dctx,   g_ctx);
    cudaGetSymbolAddress((void**)&dy,     g_y);

    static int smem_set = 0;
    if (!smem_set) {
        cudaFuncSetAttribute(gemm_mma, cudaFuncAttributeMaxDynamicSharedMemorySize, GEMM_SMEM);
        cudaFuncSetAttribute(attn_mma, cudaFuncAttributeMaxDynamicSharedMemorySize, ATTN_SMEM);
        smem_set = 1;
    }

    // 1. fold weights + biases (single kernel)
    prep_gemmAB<<<dim3(4, 4, 5), 256>>>(Win, Wq, Wk, Wv, Wfc, Wout,
                                        bin_, bq, bk, bv, bout, bfc);

    // 2. fused qkv projection: [8192,256] @ [768,256]^T   (tf32, 3-stage cp.async)
    gemm_mma<<<dim3(LDQKV / 128, MROWS / 128), 256, GEMM_SMEM>>>(mod, dWeff, dbeff, nullptr, dqkv, LDQKV, ND);

    // 3. banded attention (tensor cores, 128 queries/block)
    attn_mma<<<dim3(SQ / 128, NB * NH), 256, ATTN_SMEM>>>(req, dctx);

    // 4. fused out_proj+fc with residual: ctx @ (Wfc@Wout)^T + bcomb + mod
    gemm_mma<<<dim3(ND / 128, MROWS / 128), 256, GEMM_SMEM>>>(dctx, dWcomb, dbcomb, mod, dy, ND, NE);

    // 5. layernorm
    ln_kernel<<<MROWS / 8, 256>>>(gamma, beta, out);
}

// round 10
// speedup vs baseline: 1.0238x; 1.0238x over previous
#include <cuda_runtime.h>
#include <math_constants.h>
#include <cstdint>

#define SQ 2048
#define NB 4
#define ND 256
#define NE 256
#define NH 8
#define HD 32
#define MROWS (SQ*NB)       // 8192
#define LDQKV (3*NE)        // 768

// ---------------- scratch (device globals; no allocation) ----------------
__device__ __align__(16) float g_Weff[3*NE*ND];
__device__ __align__(16) float g_beff[3*NE];
__device__ __align__(16) float g_Wcomb[ND*NE];
__device__ __align__(16) float g_bcomb[ND];
__device__ __align__(16) float g_qkv[(size_t)MROWS*LDQKV];
__device__ __align__(16) float g_ctx[(size_t)MROWS*NE];
__device__ __align__(16) float g_y[(size_t)MROWS*ND];

extern __shared__ float sdyn[];

// ---------------- helpers ----------------
__device__ __forceinline__ void mma_tf32(float c[4],
                                         uint32_t a0, uint32_t a1, uint32_t a2, uint32_t a3,
                                         uint32_t b0, uint32_t b1)
{
    asm volatile("mma.sync.aligned.m16n8k8.row.col.f32.tf32.tf32.f32 "
                 "{%0,%1,%2,%3}, {%4,%5,%6,%7}, {%8,%9}, {%0,%1,%2,%3};"
                 : "+f"(c[0]), "+f"(c[1]), "+f"(c[2]), "+f"(c[3])
                 : "r"(a0), "r"(a1), "r"(a2), "r"(a3), "r"(b0), "r"(b1));
}

__device__ __forceinline__ void cp16(void* smem_dst, const void* gmem_src) {
    uint32_t sa = (uint32_t)__cvta_generic_to_shared(smem_dst);
    asm volatile("cp.async.cg.shared.global [%0], [%1], 16;\n" :: "r"(sa), "l"(gmem_src));
}

// ---------------- prep: 4 small 256^3 products + bias folds ----------------
// z<4 : weight products (SIMT 64x64 tiles).  z==4 : bias folds (16 blocks x 64 outputs).
__global__ void prep_gemmAB(const float* __restrict__ Win,
                            const float* __restrict__ Wq, const float* __restrict__ Wk,
                            const float* __restrict__ Wv, const float* __restrict__ Wfc,
                            const float* __restrict__ Wout,
                            const float* __restrict__ bin_, const float* __restrict__ bq,
                            const float* __restrict__ bk, const float* __restrict__ bv,
                            const float* __restrict__ bout, const float* __restrict__ bfc)
{
    const int t = threadIdx.x;
    if (blockIdx.z == 4) {
        // ---- bias folds: 1024 outputs over 16 blocks ----
        int xb = blockIdx.y * 4 + blockIdx.x;      // 0..15
        int warp = t >> 5, lane = t & 31;
        #pragma unroll
        for (int o = 0; o < 8; o++) {
            int wid = xb * 64 + warp * 8 + o;      // 0..1023
            const float* row; const float* vec; float base;
            if (wid < 3*NE) {
                int tt = wid >> 8;
                row = Win + (size_t)wid * NE;
                vec = (tt == 0) ? bq : (tt == 1) ? bk : bv;
                base = bin_[wid];
            } else {
                int r = wid - 3*NE;
                row = Wfc + (size_t)r * NE;
                vec = bout;
                base = bfc[r];
            }
            float s = 0.f;
            #pragma unroll
            for (int u = 0; u < 8; u++) s += row[u*32 + lane] * vec[u*32 + lane];
            #pragma unroll
            for (int off = 16; off >= 1; off >>= 1) s += __shfl_xor_sync(0xffffffffu, s, off);
            if (lane == 0) {
                if (wid < 3*NE) g_beff[wid] = base + s;
                else            g_bcomb[wid - 3*NE] = base + s;
            }
        }
        return;
    }

    __shared__ __align__(16) float As[16][68];   // [c][r]
    __shared__ __align__(16) float Bs[16][68];   // [c][d]
    const int tt = blockIdx.z;
    const float* A; const float* B; float* C;
    if (tt < 3) { A = Win + (size_t)tt*NE*NE; B = (tt==0)?Wq:(tt==1)?Wk:Wv; C = g_Weff + (size_t)tt*NE*ND; }
    else        { A = Wfc; B = Wout; C = g_Wcomb; }

    const int m0  = blockIdx.y * 64;
    const int d0  = blockIdx.x * 64;
    const int lrow = t >> 2;
    const int lc4  = (t & 3) << 2;
    const int brow = t >> 4;
    const int bc4  = (t & 15) << 2;
    const int ty = t >> 4, tx = t & 15;

    float acc[4][4] = {};
    for (int k0 = 0; k0 < NE; k0 += 16) {
        float4 av = *(const float4*)&A[(size_t)(m0 + lrow)*NE + k0 + lc4];
        As[lc4+0][lrow] = av.x; As[lc4+1][lrow] = av.y;
        As[lc4+2][lrow] = av.z; As[lc4+3][lrow] = av.w;
        *(float4*)&Bs[brow][bc4] = *(const float4*)&B[(size_t)(k0 + brow)*NE + d0 + bc4];
        __syncthreads();
        #pragma unroll
        for (int kk = 0; kk < 16; kk++) {
            float4 a4 = *(const float4*)&As[kk][ty << 2];
            float4 b4 = *(const float4*)&Bs[kk][tx << 2];
            float ar[4] = {a4.x, a4.y, a4.z, a4.w};
            float br[4] = {b4.x, b4.y, b4.z, b4.w};
            #pragma unroll
            for (int i = 0; i < 4; i++)
                #pragma unroll
                for (int j = 0; j < 4; j++)
                    acc[i][j] += ar[i] * br[j];
        }
        __syncthreads();
    }
    #pragma unroll
    for (int i = 0; i < 4; i++) {
        float4 o = {acc[i][0], acc[i][1], acc[i][2], acc[i][3]};
        *(float4*)&C[(size_t)(m0 + (ty<<2) + i)*NE + d0 + (tx<<2)] = o;
    }
}

// ---------------- tensor-core GEMM, 3-stage cp.async pipeline ----------------
// C[M,N] = A[M,K] @ W[N,K]^T + bias (+resid). Block tile 128x128, BK=32,
// 256 threads, warp tile 64x32. One __syncthreads per K-tile.
#define GST 36
#define GSTAGE (128*GST)
#define GEMM_SMEM (6*GSTAGE*(int)sizeof(float))   // 3 stages * (A+B) = 110592 B
__global__ void __launch_bounds__(256) gemm_mma(const float* __restrict__ A,
                                                const float* __restrict__ W,
                                                const float* __restrict__ bias,
                                                const float* __restrict__ resid,
                                                float* __restrict__ C, int N, int K)
{
    const int tid = threadIdx.x;
    const int m0 = blockIdx.y * 128;
    const int n0 = blockIdx.x * 128;
    const int warp = tid >> 5;
    const int lane = tid & 31;
    const int wm = warp >> 2;
    const int wn = warp & 3;
    const int grp = lane >> 2;
    const int tig = lane & 3;
    const int ldr = tid >> 3;
    const int ldc = (tid & 7) << 2;

    const int T = K >> 5;
    float acc[4][4][4] = {};

    // prefetch stages 0,1
    #pragma unroll
    for (int s = 0; s < 2; s++) {
        float* As = sdyn + s*2*GSTAGE;
        float* Bs = As + GSTAGE;
        int k0 = s << 5;
        #pragma unroll
        for (int p = 0; p < 4; p++) {
            int row = ldr + p * 32;
            cp16(&As[row*GST + ldc], &A[(size_t)(m0 + row)*K + k0 + ldc]);
            cp16(&Bs[row*GST + ldc], &W[(size_t)(n0 + row)*K + k0 + ldc]);
        }
        asm volatile("cp.async.commit_group;\n");
    }

    for (int t = 0; t < T; t++) {
        if (t + 1 < T) asm volatile("cp.async.wait_group 1;\n");
        else           asm volatile("cp.async.wait_group 0;\n");
        __syncthreads();

        if (t + 2 < T) {
            int s = (t + 2) % 3;
            int k0 = (t + 2) << 5;
            float* As = sdyn + s*2*GSTAGE;
            float* Bs = As + GSTAGE;
            #pragma unroll
            for (int p = 0; p < 4; p++) {
                int row = ldr + p * 32;
                cp16(&As[row*GST + ldc], &A[(size_t)(m0 + row)*K + k0 + ldc]);
                cp16(&Bs[row*GST + ldc], &W[(size_t)(n0 + row)*K + k0 + ldc]);
            }
            asm volatile("cp.async.commit_group;\n");
        }

        const float* As = sdyn + (t % 3)*2*GSTAGE;
        const float* Bs = As + GSTAGE;
        #pragma unroll
        for (int kk = 0; kk < 32; kk += 8) {
            uint32_t af[4][4], bf[4][2];
            #pragma unroll
            for (int mt = 0; mt < 4; mt++) {
                int r = (wm*64 + mt*16 + grp) * GST;
                af[mt][0] = __float_as_uint(As[r + kk + tig]);
                af[mt][1] = __float_as_uint(As[r + 8*GST + kk + tig]);
                af[mt][2] = __float_as_uint(As[r + kk + 4 + tig]);
                af[mt][3] = __float_as_uint(As[r + 8*GST + kk + 4 + tig]);
            }
            #pragma unroll
            for (int nt = 0; nt < 4; nt++) {
                int c = (wn*32 + nt*8 + grp) * GST;
                bf[nt][0] = __float_as_uint(Bs[c + kk + tig]);
                bf[nt][1] = __float_as_uint(Bs[c + kk + 4 + tig]);
            }
            #pragma unroll
            for (int mt = 0; mt < 4; mt++)
                #pragma unroll
                for (int nt = 0; nt < 4; nt++)
                    mma_tf32(acc[mt][nt], af[mt][0], af[mt][1], af[mt][2], af[mt][3],
                             bf[nt][0], bf[nt][1]);
        }
    }

    #pragma unroll
    for (int mt = 0; mt < 4; mt++) {
        #pragma unroll
        for (int nt = 0; nt < 4; nt++) {
            int col = n0 + wn*32 + nt*8 + 2*tig;
            float bx = bias[col], by = bias[col + 1];
            int r0 = m0 + wm*64 + mt*16 + grp;
            float2 o0 = {acc[mt][nt][0] + bx, acc[mt][nt][1] + by};
            float2 o1 = {acc[mt][nt][2] + bx, acc[mt][nt][3] + by};
            if (resid) {
                float2 r0v = *(const float2*)&resid[(size_t)r0 * N + col];
                float2 r1v = *(const float2*)&resid[(size_t)(r0 + 8) * N + col];
                o0.x += r0v.x; o0.y += r0v.y;
                o1.x += r1v.x; o1.y += r1v.y;
            }
            *(float2*)&C[(size_t)r0 * N + col] = o0;
            *(float2*)&C[(size_t)(r0 + 8) * N + col] = o1;
        }
    }
}

// ---------------- banded attention via tensor cores ----------------
// Block: 128 queries x one (b,h), 256 threads (8 warps), warp owns 16 queries.
// Per warp: S[16x64] = Q @ K^T over a 64-key window starting at wbase+w*16,
// masked softmax in registers, C[16x32] = P @ V. Supports req <= 24.
#define KST 36     // sK row stride
#define VST 180    // sVT row stride (mod 32 = 20, conflict-free frag reads)
#define QST 36     // sQ row stride
#define PST 68     // sP row stride
#define KROWS 176
#define SK_F   (KROWS*KST)           // 6336
#define SVT_F  (32*VST)              // 5760
#define SU_F   (8*16*PST)            // 8704 (>= 128*QST = 4608)
#define ATTN_SMEM ((SK_F + SVT_F + SU_F)*(int)sizeof(float))   // 83200 B
__global__ void __launch_bounds__(256) attn_mma(const int* __restrict__ reqp,
                                                float* __restrict__ ctx)
{
    float* sK  = sdyn;
    float* sVT = sdyn + SK_F;
    float* sU  = sdyn + SK_F + SVT_F;

    const float* qkv = g_qkv;
    const int req = *reqp;
    const int bh = blockIdx.y;
    const int b = bh >> 3;
    const int hoff = (bh & 7) * HD;
    const int q0 = blockIdx.x * 128;
    const int wbase = q0 - (req - 1);

    const int tid = threadIdx.x;
    const int w = tid >> 5;
    const int lane = tid & 31;
    const int grp = lane >> 2;
    const int tig = lane & 3;
    const float scale = rsqrtf((float)HD);

    // ---- stage Q (scaled), K, V^T (raw f32; MMA truncates to tf32) ----
    #pragma unroll
    for (int u = tid; u < 128*8; u += 256) {         // Q: 128 rows x 8 float4
        int r = u >> 3, c4 = (u & 7) << 2;
        float4 v = *(const float4*)&qkv[(size_t)((q0 + r)*NB + b)*LDQKV + hoff + c4];
        sU[r*QST + c4 + 0] = v.x * scale;
        sU[r*QST + c4 + 1] = v.y * scale;
        sU[r*QST + c4 + 2] = v.z * scale;
        sU[r*QST + c4 + 3] = v.w * scale;
    }
    for (int u = tid; u < KROWS*8; u += 256) {       // K + V: 176 rows x 8 float4
        int r = u >> 3, c4 = (u & 7) << 2;
        int key = wbase + r;
        float4 kv = {0.f, 0.f, 0.f, 0.f}, vv = {0.f, 0.f, 0.f, 0.f};
        if (key >= 0 && key < SQ) {
            size_t base = (size_t)(key*NB + b)*LDQKV + hoff + c4;
            kv = *(const float4*)&qkv[base + NE];
            vv = *(const float4*)&qkv[base + 2*NE];
        }
        sK[r*KST + c4 + 0] = kv.x;
        sK[r*KST + c4 + 1] = kv.y;
        sK[r*KST + c4 + 2] = kv.z;
        sK[r*KST + c4 + 3] = kv.w;
        sVT[(c4+0)*VST + r] = vv.x;
        sVT[(c4+1)*VST + r] = vv.y;
        sVT[(c4+2)*VST + r] = vv.z;
        sVT[(c4+3)*VST + r] = vv.w;
    }
    __syncthreads();

    // ---- scores: S[16x64] = Q @ K^T (keys wbase + w*16 + 0..63) ----
    float sc[8][4] = {};
    #pragma unroll
    for (int ks = 0; ks < 4; ks++) {
        int kk = ks * 8;
        uint32_t af[4], bf[8][2];
        {
            int r = (w*16 + grp) * QST;
            af[0] = __float_as_uint(sU[r + kk + tig]);
            af[1] = __float_as_uint(sU[r + 8*QST + kk + tig]);
            af[2] = __float_as_uint(sU[r + kk + 4 + tig]);
            af[3] = __float_as_uint(sU[r + 8*QST + kk + 4 + tig]);
        }
        #pragma unroll
        for (int nt = 0; nt < 8; nt++) {
            int r = (w*16 + nt*8 + grp) * KST;
            bf[nt][0] = __float_as_uint(sK[r + kk + tig]);
            bf[nt][1] = __float_as_uint(sK[r + kk + 4 + tig]);
        }
        #pragma unroll
        for (int nt = 0; nt < 8; nt++)
            mma_tf32(sc[nt], af[0], af[1], af[2], af[3], bf[nt][0], bf[nt][1]);
    }

    // ---- mask + softmax (registers) ----
    const int iw = q0 + w*16;
    const int jw = wbase + w*16;
    float mx0 = -CUDART_INF_F, mx1 = -CUDART_INF_F;
    {
        int i0 = iw + grp, i1 = i0 + 8;
        #pragma unroll
        for (int nt = 0; nt < 8; nt++) {
            int j0 = jw + nt*8 + 2*tig;
            int j1 = j0 + 1;
            bool g0 = (j0 >= 0) & (j0 < SQ);
            bool g1 = (j1 >= 0) & (j1 < SQ);
            float* c = sc[nt];
            c[0] = (g0 && abs(i0 - j0) < req) ? c[0] : -CUDART_INF_F;
            c[1] = (g1 && abs(i0 - j1) < req) ? c[1] : -CUDART_INF_F;
            c[2] = (g0 && abs(i1 - j0) < req) ? c[2] : -CUDART_INF_F;
            c[3] = (g1 && abs(i1 - j1) < req) ? c[3] : -CUDART_INF_F;
            mx0 = fmaxf(mx0, fmaxf(c[0], c[1]));
            mx1 = fmaxf(mx1, fmaxf(c[2], c[3]));
        }
    }
    #pragma unroll
    for (int o = 1; o <= 2; o <<= 1) {
        mx0 = fmaxf(mx0, __shfl_xor_sync(0xffffffffu, mx0, o));
        mx1 = fmaxf(mx1, __shfl_xor_sync(0xffffffffu, mx1, o));
    }
    float s0 = 0.f, s1 = 0.f;
    #pragma unroll
    for (int nt = 0; nt < 8; nt++) {
        float* c = sc[nt];
        c[0] = __expf(c[0] - mx0);
        c[1] = __expf(c[1] - mx0);
        c[2] = __expf(c[2] - mx1);
        c[3] = __expf(c[3] - mx1);
        s0 += c[0] + c[1];
        s1 += c[2] + c[3];
    }
    #pragma unroll
    for (int o = 1; o <= 2; o <<= 1) {
        s0 += __shfl_xor_sync(0xffffffffu, s0, o);
        s1 += __shfl_xor_sync(0xffffffffu, s1, o);
    }
    float rs0 = 1.f / s0, rs1 = 1.f / s1;

    // ---- store P into union region (overwrites Q) ----
    __syncthreads();   // all warps done reading sQ
    float* sP = sU + w * (16*PST);
    #pragma unroll
    for (int nt = 0; nt < 8; nt++) {
        float* c = sc[nt];
        int r0 = grp * PST + nt*8 + 2*tig;
        *(float2*)&sP[r0]           = make_float2(c[0], c[1]);
        *(float2*)&sP[r0 + 8*PST]   = make_float2(c[2], c[3]);
    }
    __syncwarp();

    // ---- ctx: C[16x32] = P[16x64] @ V[64x32] ----
    float ao[4][4] = {};
    #pragma unroll
    for (int ks = 0; ks < 8; ks++) {
        int kk = ks * 8;
        uint32_t af[4], bf[4][2];
        af[0] = __float_as_uint(sP[grp*PST + kk + tig]);
        af[1] = __float_as_uint(sP[(grp+8)*PST + kk + tig]);
        af[2] = __float_as_uint(sP[grp*PST + kk + 4 + tig]);
        af[3] = __float_as_uint(sP[(grp+8)*PST + kk + 4 + tig]);
        #pragma unroll
        for (int nt = 0; nt < 4; nt++) {
            int r = (nt*8 + grp) * VST + w*16;
            bf[nt][0] = __float_as_uint(sVT[r + kk + tig]);
            bf[nt][1] = __float_as_uint(sVT[r + kk + 4 + tig]);
        }
        #pragma unroll
        for (int nt = 0; nt < 4; nt++)
            mma_tf32(ao[nt], af[0], af[1], af[2], af[3], bf[nt][0], bf[nt][1]);
    }

    // ---- epilogue: divide by row sums, write ctx ----
    {
        int i0 = iw + grp;
        #pragma unroll
        for (int nt = 0; nt < 4; nt++) {
            int dcol = hoff + nt*8 + 2*tig;
            float2 o0 = {ao[nt][0] * rs0, ao[nt][1] * rs0};
            float2 o1 = {ao[nt][2] * rs1, ao[nt][3] * rs1};
            *(float2*)&ctx[(size_t)(i0*NB + b)*NE + dcol] = o0;
            *(float2*)&ctx[(size_t)((i0 + 8)*NB + b)*NE + dcol] = o1;
        }
    }
}

// ---------------- layernorm (warp per row of 256, float4) ----------------
__global__ void ln_kernel(const float* __restrict__ gamma, const float* __restrict__ beta,
                          float* __restrict__ out)
{
    int row = blockIdx.x * 8 + (threadIdx.x >> 5);
    int lane = threadIdx.x & 31;
    const float* yr = g_y + (size_t)row * ND;
    float4 a = *(const float4*)&yr[lane * 4];
    float4 c = *(const float4*)&yr[128 + lane * 4];
    float s  = a.x + a.y + a.z + a.w + c.x + c.y + c.z + c.w;
    float s2 = a.x*a.x + a.y*a.y + a.z*a.z + a.w*a.w
             + c.x*c.x + c.y*c.y + c.z*c.z + c.w*c.w;
    #pragma unroll
    for (int o = 16; o >= 1; o >>= 1) {
        s  += __shfl_xor_sync(0xffffffffu, s, o);
        s2 += __shfl_xor_sync(0xffffffffu, s2, o);
    }
    float mu  = s * (1.f / ND);
    float var = s2 * (1.f / ND) - mu * mu;
    float inv = rsqrtf(var + 1e-6f);
    float4 g0 = *(const float4*)&gamma[lane * 4];
    float4 g1 = *(const float4*)&gamma[128 + lane * 4];
    float4 b0 = *(const float4*)&beta[lane * 4];
    float4 b1 = *(const float4*)&beta[128 + lane * 4];
    float4 o0 = {(a.x - mu)*inv*g0.x + b0.x, (a.y - mu)*inv*g0.y + b0.y,
                 (a.z - mu)*inv*g0.z + b0.z, (a.w - mu)*inv*g0.w + b0.w};
    float4 o1 = {(c.x - mu)*inv*g1.x + b1.x, (c.y - mu)*inv*g1.y + b1.y,
                 (c.z - mu)*inv*g1.z + b1.z, (c.w - mu)*inv*g1.w + b1.w};
    *(float4*)&out[(size_t)row * ND + lane * 4] = o0;
    *(float4*)&out[(size_t)row * ND + 128 + lane * 4] = o1;
}

// ---------------- launch ----------------
extern "C" void kernel_launch(void* const* d_in, const int* in_sizes, int n_in,
                              void* d_out, int out_size)
{
    const float* mod  = (const float*)d_in[0];
    const float* Wq   = (const float*)d_in[2];
    const float* bq   = (const float*)d_in[3];
    const float* Wk   = (const float*)d_in[4];
    const float* bk   = (const float*)d_in[5];
    const float* Wv   = (const float*)d_in[6];
    const float* bv   = (const float*)d_in[7];
    const float* Win  = (const float*)d_in[8];
    const float* bin_ = (const float*)d_in[9];
    const float* Wout = (const float*)d_in[10];
    const float* bout = (const float*)d_in[11];
    const float* Wfc  = (const float*)d_in[12];
    const float* bfc  = (const float*)d_in[13];
    const float* gamma= (const float*)d_in[14];
    const float* beta = (const float*)d_in[15];
    const int*   req  = (const int*)d_in[16];
    float* out = (float*)d_out;

    float *dWeff, *dbeff, *dWcomb, *dbcomb, *dqkv, *dctx, *dy;
    cudaGetSymbolAddress((void**)&dWeff,  g_Weff);
    cudaGetSymbolAddress((void**)&dbeff,  g_beff);
    cudaGetSymbolAddress((void**)&dWcomb, g_Wcomb);
    cudaGetSymbolAddress((void**)&dbcomb, g_bcomb);
    cudaGetSymbolAddress((void**)&dqkv,   g_qkv);
    cudaGetSymbolAddress((void**)&dctx,   g_ctx);
    cudaGetSymbolAddress((void**)&dy,     g_y);

    static int smem_set = 0;
    if (!smem_set) {
        cudaFuncSetAttribute(gemm_mma, cudaFuncAttributeMaxDynamicSharedMemorySize, GEMM_SMEM);
        cudaFuncSetAttribute(attn_mma, cudaFuncAttributeMaxDynamicSharedMemorySize, ATTN_SMEM);
        smem_set = 1;
    }

    // 1. fold weights + biases (single kernel)
    prep_gemmAB<<<dim3(4, 4, 5), 256>>>(Win, Wq, Wk, Wv, Wfc, Wout,
                                        bin_, bq, bk, bv, bout, bfc);

    // 2. fused qkv projection: [8192,256] @ [768,256]^T   (tf32, 3-stage cp.async)
    gemm_mma<<<dim3(LDQKV / 128, MROWS / 128), 256, GEMM_SMEM>>>(mod, dWeff, dbeff, nullptr, dqkv, LDQKV, ND);

    // 3. banded attention (tensor cores, 128 queries/block)
    attn_mma<<<dim3(SQ / 128, NB * NH), 256, ATTN_SMEM>>>(req, dctx);

    // 4. fused out_proj+fc with residual: ctx @ (Wfc@Wout)^T + bcomb + mod
    gemm_mma<<<dim3(ND / 128, MROWS / 128), 256, GEMM_SMEM>>>(dctx, dWcomb, dbcomb, mod, dy, ND, NE);

    // 5. layernorm
    ln_kernel<<<MROWS / 8, 256>>>(gamma, beta, out);
}